// round 12
// baseline (speedup 1.0000x reference)
#include <cuda_runtime.h>

#define NS 512
#define HH 256
#define WW 256
#define HW (HH * WW)
#define EPSF 1e-6f
#define L2E 1.4426950408889634f
#define HPX (1.0f / 256.0f)

typedef unsigned long long u64;

__device__ float  g_red[512];
__device__ unsigned g_done;    // zero-init; last block restores to 0

__device__ __forceinline__ u64 ffma2(u64 a, u64 b, u64 c) {
    u64 d;
    asm("fma.rn.f32x2 %0, %1, %2, %3;" : "=l"(d) : "l"(a), "l"(b), "l"(c));
    return d;
}
__device__ __forceinline__ u64 fmul2(u64 a, u64 b) {
    u64 d;
    asm("mul.rn.f32x2 %0, %1, %2;" : "=l"(d) : "l"(a), "l"(b));
    return d;
}
__device__ __forceinline__ u64 pack2(float lo, float hi) {
    u64 d;
    asm("mov.b64 %0, {%1, %2};" : "=l"(d) : "f"(lo), "f"(hi));
    return d;
}
__device__ __forceinline__ void unpack2(u64 v, float& lo, float& hi) {
    asm("mov.b64 {%0, %1}, %2;" : "=f"(lo), "=f"(hi) : "l"(v));
}
__device__ __forceinline__ float ex2f(float x) {
    float r;
    asm("ex2.approx.ftz.f32 %0, %1;" : "=f"(r) : "f"(x));
    return r;
}
__device__ __forceinline__ void lds_v4f(unsigned addr, float4& v) {
    asm("ld.shared.v4.f32 {%0, %1, %2, %3}, [%4];"
        : "=f"(v.x), "=f"(v.y), "=f"(v.z), "=f"(v.w) : "r"(addr));
}
__device__ __forceinline__ void lds_v2u64(unsigned addr, u64& a, u64& b) {
    asm("ld.shared.v2.u64 {%0, %1}, [%2];" : "=l"(a), "=l"(b) : "r"(addr));
}

// ---------------------------------------------------------------------------
// Single kernel: 512 blocks x 512 threads. Block = half-row (128 px).
// Phase 1: per-stroke params inline, 1 stroke/thread (512 = NS) -> shared.
// Phase 2: 16 warps x 32-stroke slices; lane owns 4 contiguous px; 4-px
//          packed chain of serial depth 1 (K3 precomputed); per stroke:
//          3 LDS + 4 FMA + 2 EX2 + ~3 mul/pack + 6 ffma2.
// Phase 3: 16-warp smem reduction (24 KB, unioned with 32 KB params),
//          fused canvas+sigmoid+out+MSE; last-done block -> loss.
// Param layout (16-float stride): {a,b,cc,bh} {K,K3,w0,w0} {w1,w1,w2,w2}
// ---------------------------------------------------------------------------
__global__ void __launch_bounds__(512) mega_kernel(
    const float* __restrict__ canvas,
    const float* __restrict__ target,
    const float* __restrict__ offset,
    const float* __restrict__ sigma,
    const float* __restrict__ theta,
    const float* __restrict__ color,
    const float* __restrict__ alpha,
    float* __restrict__ out,
    int out_size)
{
    __shared__ float sh[8192];   // 32 KB: params; later reduction buffer

    const int tid = threadIdx.x;
    const int lane = tid & 31;
    const int wid = tid >> 5;
    const int half = blockIdx.x & 1;
    const int row = blockIdx.x >> 1;
    const float rowy = (float)row * HPX;

    // ---- Phase 1: full per-stroke params inline, one stroke per thread ----
    {
        const int n = tid;
        const float ox = offset[2 * n + 0];
        const float oy = offset[2 * n + 1];
        const float sg0 = sigma[2 * n + 0];
        const float sg1 = sigma[2 * n + 1];
        const float th = theta[n];

        const float ratio = (float)WW / (float)HH;
        const float s0 = sg0 / ratio;
        float s, c;
        __sincosf(th, &s, &c);
        const float ia = __fdividef(0.5f, s0 * s0);
        const float ib = __fdividef(0.5f, sg1 * sg1);

        const float A = ia * c * c + ib * s * s;
        const float C = ia * s * s + ib * c * c;
        const float B = -2.0f * s * c * (ia + ib);

        const float Xm = (float)(WW - 1) / (float)WW;
        const float Ym = (float)(HH - 1) / (float)HH;
        const float x0d = -ox, x1d = Xm - ox;
        const float y0d = -oy, y1d = Ym - oy;

        float best = 3.4e38f, bdx = 0.0f, bdy = 0.0f;
        if (x0d <= 0.0f && x1d >= 0.0f && y0d <= 0.0f && y1d >= 0.0f) {
            best = 0.0f; bdx = 0.0f; bdy = 0.0f;
        }
        const float i2A = __fdividef(-0.5f, A);
        const float i2C = __fdividef(-0.5f, C);
        #pragma unroll
        for (int e = 0; e < 2; e++) {
            float ex = e ? x1d : x0d;
            float dyv = fminf(fmaxf(B * ex * i2C, y0d), y1d);
            float q = fmaf(A * ex, ex, fmaf(B * ex, dyv, C * dyv * dyv));
            if (q < best) { best = q; bdx = ex; bdy = dyv; }
        }
        #pragma unroll
        for (int e = 0; e < 2; e++) {
            float ey = e ? y1d : y0d;
            float dxv = fminf(fmaxf(B * ey * i2A, x0d), x1d);
            float q = fmaf(A * dxv, dxv, fmaf(B * dxv, ey, C * ey * ey));
            if (q < best) { best = q; bdx = dxv; bdy = ey; }
        }

        const float jx = floorf((bdx + ox) * (float)WW) - 1.0f;
        const float iy = floorf((bdy + oy) * (float)HH) - 1.0f;
        float mq = 3.4e38f;
        #pragma unroll
        for (int a2 = 0; a2 < 4; a2++) {
            float jj = fminf(fmaxf(jx + (float)a2, 0.0f), (float)(WW - 1));
            float dxv = jj * (1.0f / (float)WW) - ox;
            #pragma unroll
            for (int b2 = 0; b2 < 4; b2++) {
                float ii = fminf(fmaxf(iy + (float)b2, 0.0f), (float)(HH - 1));
                float dyv = ii * (1.0f / (float)HH) - oy;
                float q = fmaf(A * dxv, dxv, fmaf(B * dxv, dyv, C * dyv * dyv));
                mq = fminf(mq, q);
            }
        }

        const float maxpdf = __expf(-mq);
        const float scale = __fdividef(maxpdf, maxpdf + EPSF);
        const float al = alpha[n];
        const float w0 = al * color[3 * n + 0] * scale;
        const float w1 = al * color[3 * n + 1] * scale;
        const float w2 = al * color[3 * n + 2] * scale;

        const float aL  = -L2E * A;
        const float bL0 = 2.0f * L2E * A * ox;
        const float bL1 = -L2E * B;
        const float cL0 = L2E * (mq - A * ox * ox);
        const float cL1 = L2E * B * ox;
        const float cL2 = -L2E * C;
        const float K = exp2f(2.0f * aL * HPX * HPX);
        const float K3 = K * K * K;

        const float dy = rowy - oy;
        const float b = fmaf(bL1, dy, bL0);
        const float cc = fmaf(fmaf(cL2, dy, cL1), dy, cL0);

        float4* d = (float4*)&sh[n * 16];
        d[0] = make_float4(aL, b, cc, b * HPX);   // a, b, cc, bh
        d[1] = make_float4(K, K3, w0, w0);        // {K,K3} {w0,w0}
        d[2] = make_float4(w1, w1, w2, w2);       // {w1,w1} {w2,w2}
    }
    __syncthreads();

    // ---- Phase 2: warp wid handles strokes [wid*32, wid*32+32) ------------
    const float x0 = (float)(half * 128 + lane * 4) * HPX;
    const float X1c = fmaf(2.0f * HPX, x0, HPX * HPX);

    u64 acc[3][2];
    #pragma unroll
    for (int ch = 0; ch < 3; ch++) {
        acc[ch][0] = 0ull;
        acc[ch][1] = 0ull;
    }

    const unsigned sbase = (unsigned)__cvta_generic_to_shared(sh) + wid * (32 * 64);

    #pragma unroll 8
    for (int sl = 0; sl < 32; sl++) {
        float4 q0;
        u64 KK3, ww0, ww1, ww2;
        lds_v4f(sbase + sl * 64, q0);
        lds_v2u64(sbase + sl * 64 + 16, KK3, ww0);
        lds_v2u64(sbase + sl * 64 + 32, ww1, ww2);

        const float a = q0.x, b = q0.y, cc = q0.z, bh = q0.w;
        float m0 = fmaf(fmaf(a, x0, b), x0, cc);
        float d0 = fmaf(a, X1c, bh);
        float p0 = ex2f(m0);
        float t0 = ex2f(d0);
        float p1 = p0 * t0;
        float t0sq = t0 * t0;

        u64 pk0 = pack2(p0, p1);
        u64 T = fmul2(pack2(t0sq, t0sq), KK3);
        u64 pk1 = fmul2(pk0, T);

        acc[0][0] = ffma2(pk0, ww0, acc[0][0]);
        acc[0][1] = ffma2(pk1, ww0, acc[0][1]);
        acc[1][0] = ffma2(pk0, ww1, acc[1][0]);
        acc[1][1] = ffma2(pk1, ww1, acc[1][1]);
        acc[2][0] = ffma2(pk0, ww2, acc[2][0]);
        acc[2][1] = ffma2(pk1, ww2, acc[2][1]);
    }

    // ---- Phase 3: 16-warp reduction in smem, fused epilogue ---------------
    __syncthreads();   // param reads done; sh becomes reduction buffer
    {
        // buf[w*384 + ch*128 + lane*4 + k]
        float* d = &sh[wid * 384 + lane * 4];
        #pragma unroll
        for (int ch = 0; ch < 3; ch++) {
            float v0, v1, v2, v3;
            unpack2(acc[ch][0], v0, v1);
            unpack2(acc[ch][1], v2, v3);
            *(float4*)(d + ch * 128) = make_float4(v0, v1, v2, v3);
        }
    }
    __syncthreads();

    float sq = 0.0f;
    if (tid < 384) {
        const int ch = tid >> 7;
        const int p = tid & 127;
        float sum = 0.0f;
        #pragma unroll
        for (int w = 0; w < 16; w++)
            sum += sh[w * 384 + tid];
        const int idx = ch * HW + row * WW + half * 128 + p;
        float z = canvas[idx] + sum;
        float o = __fdividef(1.0f, 1.0f + __expf(-z));
        out[idx] = o;
        float dd = o - target[idx];
        sq = fmaf(dd, dd, sq);
    }

    #pragma unroll
    for (int o2 = 16; o2 > 0; o2 >>= 1)
        sq += __shfl_down_sync(0xffffffffu, sq, o2);
    __syncthreads();          // buf reads done; reuse sh[0..63]
    if (lane == 0) sh[wid] = sq;
    __syncthreads();
    if (tid == 0) {
        float t2 = 0.f;
        #pragma unroll
        for (int k = 0; k < 12; k++) t2 += sh[k];   // warps 12..15 have sq=0
        g_red[blockIdx.x] = t2;
        __threadfence();
        unsigned prev = atomicAdd(&g_done, 1u);
        sh[32] = (prev == 511u) ? 1.0f : 0.0f;
    }
    __syncthreads();

    // ---- Final loss (last-done block) ------------------------------------
    if (sh[32] != 0.0f) {
        float pa = g_red[tid];
        float pb = fabsf(1.0f - __fdividef(sigma[2 * tid], sigma[2 * tid + 1]));
        float pc = fabsf(alpha[tid]);
        #pragma unroll
        for (int o2 = 16; o2 > 0; o2 >>= 1) {
            pa += __shfl_down_sync(0xffffffffu, pa, o2);
            pb += __shfl_down_sync(0xffffffffu, pb, o2);
            pc += __shfl_down_sync(0xffffffffu, pc, o2);
        }
        __syncthreads();
        if (lane == 0) {
            sh[wid] = pa;
            sh[16 + wid] = pb;
            sh[64 + wid] = pc;
        }
        __syncthreads();
        if (tid == 0) {
            float sa = 0.f, sb = 0.f, sc = 0.f;
            #pragma unroll
            for (int k = 0; k < 16; k++) {
                sa += sh[k];
                sb += sh[16 + k];
                sc += sh[64 + k];
            }
            float mse = sa / (float)(3 * HW);
            float sharp = sb * (0.001f / (float)NS);
            float transp = -sc * (0.001f / (float)NS);
            float psnr = -10.0f * log10f(mse + 1e-12f);
            float loss = mse + transp + sharp - psnr / 30.0f;
            if (out_size > 3 * HW) out[3 * HW] = loss;
            g_done = 0u;   // restore state for next graph replay
        }
    }
}

// ---------------------------------------------------------------------------
extern "C" void kernel_launch(void* const* d_in, const int* in_sizes, int n_in,
                              void* d_out, int out_size)
{
    const float* canvas = (const float*)d_in[0];
    const float* target = (const float*)d_in[1];
    const float* offset = (const float*)d_in[2];
    const float* sigma  = (const float*)d_in[3];
    const float* theta  = (const float*)d_in[4];
    const float* color  = (const float*)d_in[5];
    const float* alpha  = (const float*)d_in[6];
    float* out = (float*)d_out;

    mega_kernel<<<512, 512>>>(canvas, target, offset, sigma, theta, color,
                              alpha, out, out_size);
}

// round 13
// speedup vs baseline: 1.0373x; 1.0373x over previous
#include <cuda_runtime.h>

#define NS 512
#define HH 256
#define WW 256
#define HW (HH * WW)
#define EPSF 1e-6f
#define L2E 1.4426950408889634f
#define HPX (1.0f / 256.0f)

typedef unsigned long long u64;

__device__ float  g_part[4][3 * HW];   // 4 partial images (one per stroke-quad)
__device__ float  g_red[384];
__device__ unsigned g_done;            // zero-init; last combine block restores

__device__ __forceinline__ u64 ffma2(u64 a, u64 b, u64 c) {
    u64 d;
    asm("fma.rn.f32x2 %0, %1, %2, %3;" : "=l"(d) : "l"(a), "l"(b), "l"(c));
    return d;
}
__device__ __forceinline__ u64 fmul2(u64 a, u64 b) {
    u64 d;
    asm("mul.rn.f32x2 %0, %1, %2;" : "=l"(d) : "l"(a), "l"(b));
    return d;
}
__device__ __forceinline__ u64 pack2(float lo, float hi) {
    u64 d;
    asm("mov.b64 %0, {%1, %2};" : "=l"(d) : "f"(lo), "f"(hi));
    return d;
}
__device__ __forceinline__ void unpack2(u64 v, float& lo, float& hi) {
    asm("mov.b64 {%0, %1}, %2;" : "=f"(lo), "=f"(hi) : "l"(v));
}
__device__ __forceinline__ float ex2f(float x) {
    float r;
    asm("ex2.approx.ftz.f32 %0, %1;" : "=f"(r) : "f"(x));
    return r;
}
__device__ __forceinline__ void lds_v4f(unsigned addr, float4& v) {
    asm("ld.shared.v4.f32 {%0, %1, %2, %3}, [%4];"
        : "=f"(v.x), "=f"(v.y), "=f"(v.z), "=f"(v.w) : "r"(addr));
}
__device__ __forceinline__ void lds_v2u64(unsigned addr, u64& a, u64& b) {
    asm("ld.shared.v2.u64 {%0, %1}, [%2];" : "=l"(a), "=l"(b) : "r"(addr));
}

// ---------------------------------------------------------------------------
// K1: 1024 blocks x 128 threads. block = (row, stroke-quad of 128 strokes).
// Phase 1: inline per-stroke params, 1 stroke/thread (128 = quad size).
// Phase 2: 4 warps x 32-stroke slices; lane owns 8 contiguous px (full row);
//          per stroke: 3 LDS + 2 EX2 + packed geometric chain + 12 ffma2.
// Phase 3: in-block 4-warp reduction -> ONE 768-float partial per block
//          into g_part[quad].
// Param layout (16-float stride): {a,b,cc,K} {K4,K4,w0,w0} {w1,w1,w2,w2}
// ---------------------------------------------------------------------------
__global__ void __launch_bounds__(128) paint_kernel(
    const float* __restrict__ offset,
    const float* __restrict__ sigma,
    const float* __restrict__ theta,
    const float* __restrict__ color,
    const float* __restrict__ alpha)
{
    __shared__ float sh[5120];   // 8 KB params + 12 KB reduction buf = 20 KB

    const int tid = threadIdx.x;
    const int lane = tid & 31;
    const int wid = tid >> 5;
    const int quad = blockIdx.x & 3;
    const int row = blockIdx.x >> 2;
    const float rowy = (float)row * HPX;

    // ---- Phase 1: per-stroke params inline, one stroke per thread ---------
    {
        const int n = quad * 128 + tid;
        const float ox = offset[2 * n + 0];
        const float oy = offset[2 * n + 1];
        const float sg0 = sigma[2 * n + 0];
        const float sg1 = sigma[2 * n + 1];
        const float th = theta[n];

        const float ratio = (float)WW / (float)HH;
        const float s0 = sg0 / ratio;
        float s, c;
        __sincosf(th, &s, &c);
        const float ia = __fdividef(0.5f, s0 * s0);
        const float ib = __fdividef(0.5f, sg1 * sg1);

        const float A = ia * c * c + ib * s * s;
        const float C = ia * s * s + ib * c * c;
        const float B = -2.0f * s * c * (ia + ib);

        const float Xm = (float)(WW - 1) / (float)WW;
        const float Ym = (float)(HH - 1) / (float)HH;
        const float x0d = -ox, x1d = Xm - ox;
        const float y0d = -oy, y1d = Ym - oy;

        float best = 3.4e38f, bdx = 0.0f, bdy = 0.0f;
        if (x0d <= 0.0f && x1d >= 0.0f && y0d <= 0.0f && y1d >= 0.0f) {
            best = 0.0f; bdx = 0.0f; bdy = 0.0f;
        }
        const float i2A = __fdividef(-0.5f, A);
        const float i2C = __fdividef(-0.5f, C);
        #pragma unroll
        for (int e = 0; e < 2; e++) {
            float ex = e ? x1d : x0d;
            float dyv = fminf(fmaxf(B * ex * i2C, y0d), y1d);
            float q = fmaf(A * ex, ex, fmaf(B * ex, dyv, C * dyv * dyv));
            if (q < best) { best = q; bdx = ex; bdy = dyv; }
        }
        #pragma unroll
        for (int e = 0; e < 2; e++) {
            float ey = e ? y1d : y0d;
            float dxv = fminf(fmaxf(B * ey * i2A, x0d), x1d);
            float q = fmaf(A * dxv, dxv, fmaf(B * dxv, ey, C * ey * ey));
            if (q < best) { best = q; bdx = dxv; bdy = ey; }
        }

        const float jx = floorf((bdx + ox) * (float)WW) - 1.0f;
        const float iy = floorf((bdy + oy) * (float)HH) - 1.0f;
        float mq = 3.4e38f;
        #pragma unroll
        for (int a2 = 0; a2 < 4; a2++) {
            float jj = fminf(fmaxf(jx + (float)a2, 0.0f), (float)(WW - 1));
            float dxv = jj * (1.0f / (float)WW) - ox;
            #pragma unroll
            for (int b2 = 0; b2 < 4; b2++) {
                float ii = fminf(fmaxf(iy + (float)b2, 0.0f), (float)(HH - 1));
                float dyv = ii * (1.0f / (float)HH) - oy;
                float q = fmaf(A * dxv, dxv, fmaf(B * dxv, dyv, C * dyv * dyv));
                mq = fminf(mq, q);
            }
        }

        const float maxpdf = __expf(-mq);
        const float scale = __fdividef(maxpdf, maxpdf + EPSF);
        const float al = alpha[n];
        const float w0 = al * color[3 * n + 0] * scale;
        const float w1 = al * color[3 * n + 1] * scale;
        const float w2 = al * color[3 * n + 2] * scale;

        const float aL  = -L2E * A;
        const float bL0 = 2.0f * L2E * A * ox;
        const float bL1 = -L2E * B;
        const float cL0 = L2E * (mq - A * ox * ox);
        const float cL1 = L2E * B * ox;
        const float cL2 = -L2E * C;
        const float K = exp2f(2.0f * aL * HPX * HPX);
        const float K4 = (K * K) * (K * K);

        const float dy = rowy - oy;
        const float b = fmaf(bL1, dy, bL0);
        const float cc = fmaf(fmaf(cL2, dy, cL1), dy, cL0);

        float4* d = (float4*)&sh[tid * 16];
        d[0] = make_float4(aL, b, cc, K);
        d[1] = make_float4(K4, K4, w0, w0);
        d[2] = make_float4(w1, w1, w2, w2);
    }
    __syncthreads();

    // ---- Phase 2: warp wid handles strokes [wid*32, wid*32+32) ------------
    const float x0 = (float)(lane * 8) * HPX;
    const float X1c = fmaf(2.0f * HPX, x0, HPX * HPX);

    u64 acc[3][4];
    #pragma unroll
    for (int ch = 0; ch < 3; ch++)
        #pragma unroll
        for (int k = 0; k < 4; k++) acc[ch][k] = 0ull;

    const unsigned sbase = (unsigned)__cvta_generic_to_shared(sh) + wid * (32 * 64);

    #pragma unroll 4
    for (int sl = 0; sl < 32; sl++) {
        float4 q0;
        u64 K4v, ww0, ww1, ww2;
        lds_v4f(sbase + sl * 64, q0);
        lds_v2u64(sbase + sl * 64 + 16, K4v, ww0);
        lds_v2u64(sbase + sl * 64 + 32, ww1, ww2);

        const float a = q0.x, b = q0.y, cc = q0.z, K = q0.w;
        float m0 = fmaf(fmaf(a, x0, b), x0, cc);
        float d0 = fmaf(a, X1c, b * HPX);
        float p0 = ex2f(m0);
        float t0 = ex2f(d0);
        float p1 = p0 * t0;
        float t0sq = t0 * t0;
        float K2 = K * K;
        float r0 = t0sq * K;
        float r1 = r0 * K2;

        u64 pk0 = pack2(p0, p1);
        u64 T = pack2(r0, r1);
        u64 pk1 = fmul2(pk0, T);
        u64 T2 = fmul2(T, K4v);
        u64 pk2 = fmul2(pk1, T2);
        u64 T3 = fmul2(T2, K4v);
        u64 pk3 = fmul2(pk2, T3);

        acc[0][0] = ffma2(pk0, ww0, acc[0][0]);
        acc[0][1] = ffma2(pk1, ww0, acc[0][1]);
        acc[0][2] = ffma2(pk2, ww0, acc[0][2]);
        acc[0][3] = ffma2(pk3, ww0, acc[0][3]);
        acc[1][0] = ffma2(pk0, ww1, acc[1][0]);
        acc[1][1] = ffma2(pk1, ww1, acc[1][1]);
        acc[1][2] = ffma2(pk2, ww1, acc[1][2]);
        acc[1][3] = ffma2(pk3, ww1, acc[1][3]);
        acc[2][0] = ffma2(pk0, ww2, acc[2][0]);
        acc[2][1] = ffma2(pk1, ww2, acc[2][1]);
        acc[2][2] = ffma2(pk2, ww2, acc[2][2]);
        acc[2][3] = ffma2(pk3, ww2, acc[2][3]);
    }

    // ---- Phase 3: in-block 4-warp reduction -> one partial per block ------
    __syncthreads();   // param reads done
    {
        // buf at sh[2048 + w*768 + ch*256 + lane*8 + k]
        float* d = &sh[2048 + wid * 768 + lane * 8];
        #pragma unroll
        for (int ch = 0; ch < 3; ch++) {
            float v0, v1, v2, v3, v4, v5, v6, v7;
            unpack2(acc[ch][0], v0, v1);
            unpack2(acc[ch][1], v2, v3);
            unpack2(acc[ch][2], v4, v5);
            unpack2(acc[ch][3], v6, v7);
            float4* p4 = (float4*)(d + ch * 256);
            p4[0] = make_float4(v0, v1, v2, v3);
            p4[1] = make_float4(v4, v5, v6, v7);
        }
    }
    __syncthreads();

    #pragma unroll
    for (int j = 0; j < 6; j++) {
        const int off = tid + 128 * j;          // 0..767
        float sum = sh[2048 + off] + sh[2048 + 768 + off]
                  + sh[2048 + 1536 + off] + sh[2048 + 2304 + off];
        const int ch = off >> 8;
        const int p = off & 255;
        g_part[quad][ch * HW + row * WW + p] = sum;
    }
}

// ---------------------------------------------------------------------------
// K2 combine: 384 blocks x 128 threads, one float4 per thread.
// z = canvas + sum of 4 partials; out = sigmoid(z); MSE reduce; fused loss.
// ---------------------------------------------------------------------------
__global__ void __launch_bounds__(128) combine_kernel(
    const float* __restrict__ canvas,
    const float* __restrict__ target,
    const float* __restrict__ sigma,
    const float* __restrict__ alpha,
    float* __restrict__ out,
    int out_size)
{
    __shared__ float ws[4];
    __shared__ int lastflag;

    const int tid = threadIdx.x;
    const int i = blockIdx.x * 128 + tid;   // float4 index, 49152 total

    float4 sum = ((const float4*)canvas)[i];
    #pragma unroll
    for (int q = 0; q < 4; q++) {
        float4 p = ((const float4*)&g_part[q][0])[i];
        sum.x += p.x; sum.y += p.y; sum.z += p.z; sum.w += p.w;
    }
    float4 o;
    o.x = __fdividef(1.0f, 1.0f + __expf(-sum.x));
    o.y = __fdividef(1.0f, 1.0f + __expf(-sum.y));
    o.z = __fdividef(1.0f, 1.0f + __expf(-sum.z));
    o.w = __fdividef(1.0f, 1.0f + __expf(-sum.w));
    ((float4*)out)[i] = o;

    float4 tg = ((const float4*)target)[i];
    float dx = o.x - tg.x, dy = o.y - tg.y, dz = o.z - tg.z, dw = o.w - tg.w;
    float sq = fmaf(dx, dx, fmaf(dy, dy, fmaf(dz, dz, dw * dw)));

    #pragma unroll
    for (int o2 = 16; o2 > 0; o2 >>= 1)
        sq += __shfl_down_sync(0xffffffffu, sq, o2);
    if ((tid & 31) == 0) ws[tid >> 5] = sq;
    __syncthreads();
    if (tid == 0) {
        g_red[blockIdx.x] = ws[0] + ws[1] + ws[2] + ws[3];
        __threadfence();
        unsigned prev = atomicAdd(&g_done, 1u);
        lastflag = (prev == 383u) ? 1 : 0;
    }
    __syncthreads();

    if (lastflag) {
        __shared__ float sa[128], sb[128], sc2[128];
        float pa = g_red[tid] + g_red[tid + 128] + g_red[tid + 256];
        float pb = 0.f, pc = 0.f;
        #pragma unroll
        for (int k = 0; k < 4; k++) {
            int nn = tid + 128 * k;
            pb += fabsf(1.0f - __fdividef(sigma[2 * nn], sigma[2 * nn + 1]));
            pc += fabsf(alpha[nn]);
        }
        sa[tid] = pa; sb[tid] = pb; sc2[tid] = pc;
        __syncthreads();
        for (int s2 = 64; s2 > 0; s2 >>= 1) {
            if (tid < s2) {
                sa[tid] += sa[tid + s2];
                sb[tid] += sb[tid + s2];
                sc2[tid] += sc2[tid + s2];
            }
            __syncthreads();
        }
        if (tid == 0) {
            float mse = sa[0] / (float)(3 * HW);
            float sharp = sb[0] * (0.001f / (float)NS);
            float transp = -sc2[0] * (0.001f / (float)NS);
            float psnr = -10.0f * log10f(mse + 1e-12f);
            float loss = mse + transp + sharp - psnr / 30.0f;
            if (out_size > 3 * HW) out[3 * HW] = loss;
            g_done = 0u;   // restore state for next graph replay
        }
    }
}

// ---------------------------------------------------------------------------
extern "C" void kernel_launch(void* const* d_in, const int* in_sizes, int n_in,
                              void* d_out, int out_size)
{
    const float* canvas = (const float*)d_in[0];
    const float* target = (const float*)d_in[1];
    const float* offset = (const float*)d_in[2];
    const float* sigma  = (const float*)d_in[3];
    const float* theta  = (const float*)d_in[4];
    const float* color  = (const float*)d_in[5];
    const float* alpha  = (const float*)d_in[6];
    float* out = (float*)d_out;

    paint_kernel<<<1024, 128>>>(offset, sigma, theta, color, alpha);
    combine_kernel<<<384, 128>>>(canvas, target, sigma, alpha, out, out_size);
}